// round 8
// baseline (speedup 1.0000x reference)
#include <cuda_runtime.h>
#include <cuda_fp16.h>
#include <cstdint>

#define PADK 136           // halfs per smem row (128 + 8 pad) -> conflict-free LDSM
#define FULLMASK 0xffffffffu

// Scratch: per-node transformed features, fp16.
__device__ __half g_Y[(size_t)50000 * 256];
__device__ int g_idx64;

// ---------------------------------------------------------------------------
__device__ __forceinline__ unsigned sptr(const void* p) {
    return (unsigned)__cvta_generic_to_shared(p);
}
__device__ __forceinline__ void ldsm4(unsigned a, unsigned& r0, unsigned& r1,
                                      unsigned& r2, unsigned& r3) {
    asm volatile("ldmatrix.sync.aligned.m8n8.x4.shared.b16 {%0,%1,%2,%3}, [%4];\n"
                 : "=r"(r0), "=r"(r1), "=r"(r2), "=r"(r3) : "r"(a));
}
__device__ __forceinline__ void mma16816(float* c, unsigned a0, unsigned a1,
                                         unsigned a2, unsigned a3,
                                         unsigned b0, unsigned b1) {
    asm volatile(
        "mma.sync.aligned.m16n8k16.row.col.f32.f16.f16.f32 "
        "{%0,%1,%2,%3}, {%4,%5,%6,%7}, {%8,%9}, {%0,%1,%2,%3};\n"
        : "+f"(c[0]), "+f"(c[1]), "+f"(c[2]), "+f"(c[3])
        : "r"(a0), "r"(a1), "r"(a2), "r"(a3), "r"(b0), "r"(b1));
}
__device__ __forceinline__ void cp16(unsigned saddr, const void* gaddr) {
    asm volatile("cp.async.cg.shared.global [%0], [%1], 16;\n"
                 :: "r"(saddr), "l"(gaddr));
}

// ---------------------------------------------------------------------------
// Node kernel (persistent, block 512, 1 CTA/SM) — unchanged (proven).
// ---------------------------------------------------------------------------
__device__ __forceinline__ void warp_mma_32x64(const __half* Aw, const __half* Bw,
                                               float acc[2][8][4], int lane) {
    unsigned a_addr = sptr(Aw + (size_t)(lane & 15) * PADK + ((lane & 16) ? 8 : 0));
    unsigned b_addr = sptr(Bw + (size_t)((lane & 7) + ((lane & 16) ? 8 : 0)) * PADK
                              + ((lane & 8) ? 8 : 0));
    #pragma unroll
    for (int k0 = 0; k0 < 128; k0 += 16) {
        unsigned a0[4], a1[4];
        ldsm4(a_addr + k0 * 2, a0[0], a0[1], a0[2], a0[3]);
        ldsm4(a_addr + 16 * PADK * 2 + k0 * 2, a1[0], a1[1], a1[2], a1[3]);
        #pragma unroll
        for (int np = 0; np < 4; np++) {
            unsigned b0, b1, b2, b3;
            ldsm4(b_addr + (unsigned)(np * 16 * PADK * 2) + k0 * 2, b0, b1, b2, b3);
            mma16816(acc[0][2 * np],     a0[0], a0[1], a0[2], a0[3], b0, b1);
            mma16816(acc[0][2 * np + 1], a0[0], a0[1], a0[2], a0[3], b2, b3);
            mma16816(acc[1][2 * np],     a1[0], a1[1], a1[2], a1[3], b0, b1);
            mma16816(acc[1][2 * np + 1], a1[0], a1[1], a1[2], a1[3], b2, b3);
        }
    }
}

__global__ __launch_bounds__(512, 1)
void node_gemm_kernel(const float* __restrict__ x,
                      const float* __restrict__ W1,
                      const void* __restrict__ ei,
                      int n_nodes) {
    extern __shared__ __half smem[];
    __half* As0 = smem;
    __half* As1 = smem + 128 * PADK;
    __half* Ws  = smem + 2 * 128 * PADK;   // [256 out-cols][PADK k]

    const int tid = threadIdx.x;

    if (blockIdx.x == 0 && tid < 32) {
        const unsigned* w = (const unsigned*)ei;
        unsigned v = w[2 * tid + 1] | w[2 * (tid + 32) + 1];
        int any_nz = __any_sync(FULLMASK, v != 0u);
        if (tid == 0) g_idx64 = any_nz ? 0 : 1;
    }

    for (int i = tid; i < 256 * 128; i += 512) {
        int c = i & 255, k = i >> 8;
        Ws[(size_t)c * PADK + k] =
            __float2half(W1[(size_t)(k + ((c >> 7) << 7)) * 128 + (c & 127)]);
    }

    const int warp = tid >> 5, lane = tid & 31;
    const int wm = warp & 3, wn = warp >> 2;   // 4M x 4N
    const int g = lane >> 2, t = lane & 3;
    const int n_tiles = (n_nodes + 127) >> 7;

    int li = 0;
    for (int tile = blockIdx.x; tile < n_tiles; tile += gridDim.x, li++) {
        __half* As = (li & 1) ? As1 : As0;
        const int row0 = tile << 7;

        for (int i = tid; i < 128 * 32; i += 512) {
            int r = i >> 5, c4 = i & 31;
            int gr = row0 + r;
            float4 v = make_float4(0.f, 0.f, 0.f, 0.f);
            if (gr < n_nodes) v = ((const float4*)x)[(size_t)gr * 32 + c4];
            __half* dst = As + (size_t)r * PADK + c4 * 4;
            dst[0] = __float2half(v.x); dst[1] = __float2half(v.y);
            dst[2] = __float2half(v.z); dst[3] = __float2half(v.w);
        }
        __syncthreads();

        float acc[2][8][4];
        #pragma unroll
        for (int mi = 0; mi < 2; mi++)
            #pragma unroll
            for (int n8 = 0; n8 < 8; n8++)
                acc[mi][n8][0] = acc[mi][n8][1] = acc[mi][n8][2] = acc[mi][n8][3] = 0.f;

        warp_mma_32x64(As + (size_t)(wm * 32) * PADK,
                       Ws + (size_t)(wn * 64) * PADK, acc, lane);

        #pragma unroll
        for (int mi = 0; mi < 2; mi++) {
            const int r0 = row0 + wm * 32 + mi * 16 + g;
            #pragma unroll
            for (int n8 = 0; n8 < 8; n8++) {
                int col = wn * 64 + n8 * 8 + 2 * t;
                if (r0 < n_nodes)
                    *(__half2*)(g_Y + (size_t)r0 * 256 + col) =
                        __floats2half2_rn(acc[mi][n8][0], acc[mi][n8][1]);
                if (r0 + 8 < n_nodes)
                    *(__half2*)(g_Y + (size_t)(r0 + 8) * 256 + col) =
                        __floats2half2_rn(acc[mi][n8][2], acc[mi][n8][3]);
            }
        }
    }
}

// ---------------------------------------------------------------------------
// Edge kernel (persistent, block 512, 1 CTA/SM), cp.async-pipelined:
//   raw Y[src]/Y[dst] halves cp.async'd ONE TILE AHEAD into (S,D) ping-pong;
//   compute h = relu(S + D + b1) IN PLACE over S; MMA reads S via LDSM.
// Warps: 4M x 4N (32x32 tiles). Direct-STG epilogue (R4 style).
// ---------------------------------------------------------------------------
__global__ __launch_bounds__(512, 1)
void edge_kernel(const void* __restrict__ edge_index,
                 const float* __restrict__ b1,
                 const float* __restrict__ W2,
                 const float* __restrict__ b2,
                 float* __restrict__ out,
                 int n_edges) {
    extern __shared__ char dsm[];
    // S0 | D0 | S1 | D1 | W2, each 128*PADK*2 = 34816 B
    __half* Sb[2] = { (__half*)dsm, (__half*)(dsm + 2 * 34816) };
    __half* Db[2] = { (__half*)(dsm + 34816), (__half*)(dsm + 3 * 34816) };
    __half* Ws = (__half*)(dsm + 4 * 34816);

    const int tid = threadIdx.x;
    const int warp = tid >> 5, lane = tid & 31;
    const int wm = warp & 3, wn = warp >> 2;   // 4M x 4N, 32x32 warp tiles
    const int g = lane >> 2, t = lane & 3;

    // Stage W2 once (transposed; coalesced on global side)
    for (int i = tid; i < 128 * 128; i += 512) {
        int k = i >> 7, n = i & 127;
        Ws[(size_t)n * PADK + k] = __float2half(W2[i]);  // W2[k*128+n]
    }

    // Per-thread constants
    // compute-phase: fixed col chunk = (tid&15)*8 halfs -> 8 b1 floats
    const float4 bA = __ldg((const float4*)(b1 + (tid & 15) * 8));
    const float4 bB = __ldg((const float4*)(b1 + (tid & 15) * 8 + 4));
    // epilogue b2 for cols wn*32 + n8*8 + 2t
    float2 breg[4];
    #pragma unroll
    for (int n8 = 0; n8 < 4; n8++)
        breg[n8] = *(const float2*)(b2 + wn * 32 + n8 * 8 + 2 * t);

    const int is64 = g_idx64;
    const long long* idx64 = (const long long*)edge_index;
    const int*       idx32 = (const int*)edge_index;
    const int n_tiles = (n_edges + 127) >> 7;
    const int gs = gridDim.x;

    // Per-warp 8 edges: lanes 0-7 = src idx of edge (lane&7), 8-15 = dst idx.
    auto load_idx = [&](int tl) -> int {
        int myE = (tl << 7) + warp * 8 + (lane & 7);
        if (myE >= n_edges) myE = n_edges - 1;
        size_t off = (lane & 8) ? (size_t)n_edges + (size_t)myE : (size_t)myE;
        return is64 ? (int)idx64[off] : idx32[off];
    };
    // Issue one tile's gather into buffer p (vidx holds this tile's indices).
    auto issue = [&](int p, int v) {
        const unsigned chunk = (unsigned)((lane & 15) * 16);
        unsigned ss = sptr(Sb[p] + (size_t)(warp * 8) * PADK) + chunk;
        unsigned sd = sptr(Db[p] + (size_t)(warp * 8) * PADK) + chunk;
        #pragma unroll
        for (int j = 0; j < 8; j++) {
            int s = __shfl_sync(FULLMASK, v, j);
            int d = __shfl_sync(FULLMASK, v, 8 + j);
            if (lane < 16)
                cp16(ss + (unsigned)(j * PADK * 2),
                     g_Y + (size_t)s * 256 + (lane & 15) * 8);
            else
                cp16(sd + (unsigned)(j * PADK * 2),
                     g_Y + (size_t)d * 256 + 128 + (lane & 15) * 8);
        }
    };

    int tile = blockIdx.x;
    if (tile >= n_tiles) return;

    // Prologue: issue tiles t0 and t0+gs
    {
        int v0 = load_idx(tile);
        int t1 = tile + gs;
        int v1 = (t1 < n_tiles) ? load_idx(t1) : 0;
        issue(0, v0);
        asm volatile("cp.async.commit_group;\n" ::: "memory");
        if (t1 < n_tiles) issue(1, v1);
        asm volatile("cp.async.commit_group;\n" ::: "memory");
    }
    __syncthreads();   // W2 staged before first MMA

    const int crow = tid >> 4;           // 0..31 (compute-phase row base)
    const int ccol = (tid & 15) * 8;     // halfs

    int li = 0;
    int tcur = tile;
    while (true) {
        const int p = li & 1;
        const int e0 = tcur << 7;
        __half* Sp = Sb[p];
        __half* Dp = Db[p];

        // prefetch indices for tile t+2 (used at issue after MMA)
        const int t2 = tcur + 2 * gs;
        const bool more2 = t2 < n_tiles;
        int v2 = more2 ? load_idx(t2) : 0;

        // ---- wait for this tile's raw data ----
        asm volatile("cp.async.wait_group %0;\n" :: "n"(1) : "memory");
        __syncthreads();

        // ---- compute h = relu(S + D + b1) in place over S ----
        {
            uint4 vs[4], vd[4];
            #pragma unroll
            for (int c = 0; c < 4; c++) {
                int row = crow + c * 32;
                vs[c] = *(const uint4*)(Sp + (size_t)row * PADK + ccol);
                vd[c] = *(const uint4*)(Dp + (size_t)row * PADK + ccol);
            }
            #pragma unroll
            for (int c = 0; c < 4; c++) {
                const __half2* hs = (const __half2*)&vs[c];
                const __half2* hd = (const __half2*)&vd[c];
                __half2 r[4];
                float2 f0, f1;
                f0 = __half22float2(hs[0]); f1 = __half22float2(hd[0]);
                r[0] = __floats2half2_rn(fmaxf(f0.x + f1.x + bA.x, 0.f),
                                         fmaxf(f0.y + f1.y + bA.y, 0.f));
                f0 = __half22float2(hs[1]); f1 = __half22float2(hd[1]);
                r[1] = __floats2half2_rn(fmaxf(f0.x + f1.x + bA.z, 0.f),
                                         fmaxf(f0.y + f1.y + bA.w, 0.f));
                f0 = __half22float2(hs[2]); f1 = __half22float2(hd[2]);
                r[2] = __floats2half2_rn(fmaxf(f0.x + f1.x + bB.x, 0.f),
                                         fmaxf(f0.y + f1.y + bB.y, 0.f));
                f0 = __half22float2(hs[3]); f1 = __half22float2(hd[3]);
                r[3] = __floats2half2_rn(fmaxf(f0.x + f1.x + bB.z, 0.f),
                                         fmaxf(f0.y + f1.y + bB.w, 0.f));
                int row = crow + c * 32;
                *(uint4*)(Sp + (size_t)row * PADK + ccol) = *(const uint4*)r;
            }
        }
        __syncthreads();   // H ready

        // ---- 32x32 warp-tile GEMM: A = Sp (h), B = Ws ----
        float acc[2][4][4];
        #pragma unroll
        for (int mi = 0; mi < 2; mi++)
            #pragma unroll
            for (int n8 = 0; n8 < 4; n8++)
                acc[mi][n8][0] = acc[mi][n8][1] = acc[mi][n8][2] = acc[mi][n8][3] = 0.f;
        {
            unsigned a_addr = sptr(Sp + (size_t)(wm * 32 + (lane & 15)) * PADK +
                                   ((lane & 16) ? 8 : 0));
            unsigned b_addr = sptr(Ws + (size_t)(wn * 32 + (lane & 7) +
                                   ((lane & 16) ? 8 : 0)) * PADK +
                                   ((lane & 8) ? 8 : 0));
            #pragma unroll
            for (int ks = 0; ks < 8; ks++) {
                unsigned a0[4], a1[4];
                ldsm4(a_addr + ks * 32, a0[0], a0[1], a0[2], a0[3]);
                ldsm4(a_addr + 16 * PADK * 2 + ks * 32, a1[0], a1[1], a1[2], a1[3]);
                #pragma unroll
                for (int np = 0; np < 2; np++) {
                    unsigned b0, b1r_, b2r, b3;
                    ldsm4(b_addr + (unsigned)(np * 16 * PADK * 2) + ks * 32,
                          b0, b1r_, b2r, b3);
                    mma16816(acc[0][2 * np],     a0[0], a0[1], a0[2], a0[3], b0, b1r_);
                    mma16816(acc[0][2 * np + 1], a0[0], a0[1], a0[2], a0[3], b2r, b3);
                    mma16816(acc[1][2 * np],     a1[0], a1[1], a1[2], a1[3], b0, b1r_);
                    mma16816(acc[1][2 * np + 1], a1[0], a1[1], a1[2], a1[3], b2r, b3);
                }
            }
        }
        __syncthreads();   // all LDSM of Sp complete -> buffer reusable

        // ---- issue gather for tile t+2 into this buffer ----
        if (more2) issue(p, v2);
        asm volatile("cp.async.commit_group;\n" ::: "memory");  // always (count!)

        // ---- epilogue: +b2, direct float2 stores ----
        #pragma unroll
        for (int mi = 0; mi < 2; mi++) {
            const int r0 = e0 + wm * 32 + mi * 16 + g;
            #pragma unroll
            for (int n8 = 0; n8 < 4; n8++) {
                int col = wn * 32 + n8 * 8 + 2 * t;
                if (r0 < n_edges)
                    *(float2*)(out + (size_t)r0 * 128 + col) =
                        make_float2(acc[mi][n8][0] + breg[n8].x,
                                    acc[mi][n8][1] + breg[n8].y);
                if (r0 + 8 < n_edges)
                    *(float2*)(out + (size_t)(r0 + 8) * 128 + col) =
                        make_float2(acc[mi][n8][2] + breg[n8].x,
                                    acc[mi][n8][3] + breg[n8].y);
            }
        }

        const int tn = tcur + gs;
        if (tn >= n_tiles) break;
        tcur = tn; li++;
    }
    asm volatile("cp.async.wait_all;\n" ::: "memory");
}

// ---------------------------------------------------------------------------
extern "C" void kernel_launch(void* const* d_in, const int* in_sizes, int n_in,
                              void* d_out, int out_size) {
    const float* x  = (const float*)d_in[0];
    const void*  ei = d_in[1];
    const float* W1 = (const float*)d_in[2];
    const float* b1 = (const float*)d_in[3];
    const float* W2 = (const float*)d_in[4];
    const float* b2 = (const float*)d_in[5];
    float* out = (float*)d_out;

    const int n_nodes = in_sizes[0] / 128;
    const int n_edges = in_sizes[1] / 2;

    const int node_smem = (2 * 128 + 256) * PADK * (int)sizeof(__half);  // 139264
    const int edge_smem = 5 * 128 * PADK * (int)sizeof(__half);          // 174080
    static bool attr_set = false;
    if (!attr_set) {
        cudaFuncSetAttribute(node_gemm_kernel,
                             cudaFuncAttributeMaxDynamicSharedMemorySize, node_smem);
        cudaFuncSetAttribute(edge_kernel,
                             cudaFuncAttributeMaxDynamicSharedMemorySize, edge_smem);
        attr_set = true;
    }

    const int node_tiles = (n_nodes + 127) / 128;
    int g1 = node_tiles < 148 ? node_tiles : 148;
    node_gemm_kernel<<<g1, 512, node_smem>>>(x, W1, ei, n_nodes);

    const int edge_tiles = (n_edges + 127) / 128;
    int g2 = edge_tiles < 148 ? edge_tiles : 148;
    edge_kernel<<<g2, 512, edge_smem>>>(ei, b1, W2, b2, out, n_edges);
}

// round 9
// speedup vs baseline: 1.2672x; 1.2672x over previous
#include <cuda_runtime.h>
#include <cuda_fp16.h>
#include <cstdint>

#define PADK 136           // halfs per smem row (128 + 8 pad) -> conflict-free LDSM
#define FULLMASK 0xffffffffu

// Scratch: per-node transformed features, fp16.
// Y[n, 0:128] = x[n] @ W1a (src half),  Y[n,128:256] = x[n] @ W1b (dst half)
__device__ __half g_Y[(size_t)50000 * 256];
__device__ int g_idx64;

// ---------------------------------------------------------------------------
__device__ __forceinline__ unsigned sptr(const void* p) {
    return (unsigned)__cvta_generic_to_shared(p);
}
__device__ __forceinline__ void ldsm4(unsigned a, unsigned& r0, unsigned& r1,
                                      unsigned& r2, unsigned& r3) {
    asm volatile("ldmatrix.sync.aligned.m8n8.x4.shared.b16 {%0,%1,%2,%3}, [%4];\n"
                 : "=r"(r0), "=r"(r1), "=r"(r2), "=r"(r3) : "r"(a));
}
__device__ __forceinline__ void mma16816(float* c, unsigned a0, unsigned a1,
                                         unsigned a2, unsigned a3,
                                         unsigned b0, unsigned b1) {
    asm volatile(
        "mma.sync.aligned.m16n8k16.row.col.f32.f16.f16.f32 "
        "{%0,%1,%2,%3}, {%4,%5,%6,%7}, {%8,%9}, {%0,%1,%2,%3};\n"
        : "+f"(c[0]), "+f"(c[1]), "+f"(c[2]), "+f"(c[3])
        : "r"(a0), "r"(a1), "r"(a2), "r"(a3), "r"(b0), "r"(b1));
}

// ---------------------------------------------------------------------------
// Warp-level 32x64x128 GEMM.
// ---------------------------------------------------------------------------
__device__ __forceinline__ void warp_mma_32x64(const __half* Aw, const __half* Bw,
                                               float acc[2][8][4], int lane) {
    unsigned a_addr = sptr(Aw + (size_t)(lane & 15) * PADK + ((lane & 16) ? 8 : 0));
    unsigned b_addr = sptr(Bw + (size_t)((lane & 7) + ((lane & 16) ? 8 : 0)) * PADK
                              + ((lane & 8) ? 8 : 0));
    #pragma unroll
    for (int k0 = 0; k0 < 128; k0 += 16) {
        unsigned a0[4], a1[4];
        ldsm4(a_addr + k0 * 2, a0[0], a0[1], a0[2], a0[3]);
        ldsm4(a_addr + 16 * PADK * 2 + k0 * 2, a1[0], a1[1], a1[2], a1[3]);
        #pragma unroll
        for (int np = 0; np < 4; np++) {
            unsigned b0, b1, b2, b3;
            ldsm4(b_addr + (unsigned)(np * 16 * PADK * 2) + k0 * 2, b0, b1, b2, b3);
            mma16816(acc[0][2 * np],     a0[0], a0[1], a0[2], a0[3], b0, b1);
            mma16816(acc[0][2 * np + 1], a0[0], a0[1], a0[2], a0[3], b2, b3);
            mma16816(acc[1][2 * np],     a1[0], a1[1], a1[2], a1[3], b0, b1);
            mma16816(acc[1][2 * np + 1], a1[0], a1[1], a1[2], a1[3], b2, b3);
        }
    }
}

// ---------------------------------------------------------------------------
// Node kernel (persistent, block 256, 2 CTAs/SM via y-split):
//   Y[:, half*128 : +128] = x @ W1[half*128 : +128, :]
// grid (148, 2); each CTA handles one 128-col half of Y. W1 half staged once.
// ---------------------------------------------------------------------------
__global__ __launch_bounds__(256, 2)
void node_gemm_kernel(const float* __restrict__ x,
                      const float* __restrict__ W1,
                      const void* __restrict__ ei,
                      int n_nodes) {
    extern __shared__ __half smem[];
    __half* As0 = smem;                   // [128][PADK]
    __half* As1 = smem + 128 * PADK;
    __half* Ws  = smem + 2 * 128 * PADK;  // [128 cols][PADK k] for this half

    const int tid = threadIdx.x;
    const int half_sel = blockIdx.y;

    // edge_index dtype detection (int64 LE small values => odd words all 0)
    if (blockIdx.x == 0 && half_sel == 0 && tid < 32) {
        const unsigned* w = (const unsigned*)ei;
        unsigned v = w[2 * tid + 1] | w[2 * (tid + 32) + 1];
        int any_nz = __any_sync(FULLMASK, v != 0u);
        if (tid == 0) g_idx64 = any_nz ? 0 : 1;
    }

    // Stage this half of W1 once: Ws[n][k] = W1[(k + 128*half)*128 + n]
    for (int i = tid; i < 128 * 128; i += 256) {
        int k = i >> 7, n = i & 127;   // consecutive tid -> consecutive n (coalesced)
        Ws[(size_t)n * PADK + k] =
            __float2half(W1[(size_t)(k + (half_sel << 7)) * 128 + n]);
    }

    const int warp = tid >> 5, lane = tid & 31;
    const int wm = warp & 3, wn = warp >> 2;   // 4M x 2N
    const int g = lane >> 2, t = lane & 3;
    const int n_tiles = (n_nodes + 127) >> 7;

    int li = 0;
    for (int tile = blockIdx.x; tile < n_tiles; tile += gridDim.x, li++) {
        __half* As = (li & 1) ? As1 : As0;
        const int row0 = tile << 7;

        // Load x tile fp32 -> fp16 (coalesced float4, zero-pad OOB rows)
        for (int i = tid; i < 128 * 32; i += 256) {
            int r = i >> 5, c4 = i & 31;
            int gr = row0 + r;
            float4 v = make_float4(0.f, 0.f, 0.f, 0.f);
            if (gr < n_nodes) v = ((const float4*)x)[(size_t)gr * 32 + c4];
            __half* dst = As + (size_t)r * PADK + c4 * 4;
            dst[0] = __float2half(v.x); dst[1] = __float2half(v.y);
            dst[2] = __float2half(v.z); dst[3] = __float2half(v.w);
        }
        __syncthreads();

        float acc[2][8][4];
        #pragma unroll
        for (int mi = 0; mi < 2; mi++)
            #pragma unroll
            for (int n8 = 0; n8 < 8; n8++)
                acc[mi][n8][0] = acc[mi][n8][1] = acc[mi][n8][2] = acc[mi][n8][3] = 0.f;

        warp_mma_32x64(As + (size_t)(wm * 32) * PADK,
                       Ws + (size_t)(wn * 64) * PADK, acc, lane);

        __half* Yb = g_Y + (half_sel << 7);
        #pragma unroll
        for (int mi = 0; mi < 2; mi++) {
            const int r0 = row0 + wm * 32 + mi * 16 + g;
            #pragma unroll
            for (int n8 = 0; n8 < 8; n8++) {
                int col = wn * 64 + n8 * 8 + 2 * t;
                if (r0 < n_nodes)
                    *(__half2*)(Yb + (size_t)r0 * 256 + col) =
                        __floats2half2_rn(acc[mi][n8][0], acc[mi][n8][1]);
                if (r0 + 8 < n_nodes)
                    *(__half2*)(Yb + (size_t)(r0 + 8) * 256 + col) =
                        __floats2half2_rn(acc[mi][n8][2], acc[mi][n8][3]);
            }
        }
        // no second sync: next iteration writes the other A buffer
    }
}

// ---------------------------------------------------------------------------
// Edge kernel (persistent, block 256, 2 CTAs/SM) — R4 base + shfl/STG.128
// epilogue:  h = relu(Y[src,:128] + Y[dst,128:] + b1);  out = h @ W2 + b2
// ---------------------------------------------------------------------------
__global__ __launch_bounds__(256, 2)
void edge_kernel(const void* __restrict__ edge_index,
                 const float* __restrict__ b1,
                 const float* __restrict__ W2,
                 const float* __restrict__ b2,
                 float* __restrict__ out,
                 int n_edges) {
    extern __shared__ __half smem[];
    __half* Hs0 = smem;                   // [128][PADK]
    __half* Hs1 = smem + 128 * PADK;
    __half* Ws  = smem + 2 * 128 * PADK;  // [128 n][PADK k] = W2[k][n]

    const int tid = threadIdx.x;
    const int warp = tid >> 5, lane = tid & 31;
    const int wm = warp & 3, wn = warp >> 2;   // 4M x 2N
    const int g = lane >> 2, t = lane & 3;
    const bool oddt = (t & 1);

    // Stage W2 once (transposed; coalesced on global side)
    for (int i = tid; i < 128 * 128; i += 256) {
        int k = i >> 7, n = i & 127;
        Ws[(size_t)n * PADK + k] = __float2half(W2[i]);  // W2[k*128+n]
    }

    // Per-lane constants
    const float4 b1v = *(const float4*)(b1 + lane * 4);
    // epilogue columns after shfl merge: 4 cols per q
    int colq[4];
    float4 b2v[4];
    #pragma unroll
    for (int q = 0; q < 4; q++) {
        colq[q] = wn * 64 + 16 * q + (oddt ? 8 + 2 * (t - 1) : 2 * t);
        b2v[q] = *(const float4*)(b2 + colq[q]);
    }

    const int is64 = g_idx64;
    const long long* idx64 = (const long long*)edge_index;
    const int*       idx32 = (const int*)edge_index;
    const int n_tiles = (n_edges + 127) >> 7;

    int li = 0;
    for (int tile = blockIdx.x; tile < n_tiles; tile += gridDim.x, li++) {
        __half* Hs = (li & 1) ? Hs1 : Hs0;
        const int e0 = tile << 7;

        // ---- warp-cooperative gather (batched x4) ----
        {
            int myE = e0 + (warp << 4) + (lane & 15);
            if (myE >= n_edges) myE = n_edges - 1;
            size_t off = (lane < 16) ? (size_t)myE : (size_t)n_edges + (size_t)myE;
            int vidx = is64 ? (int)idx64[off] : idx32[off];

            __half* Hrow = Hs + (size_t)(warp << 4) * PADK + lane * 4;
            #pragma unroll
            for (int i = 0; i < 16; i += 4) {
                uint2 va[4], vd[4];
                #pragma unroll
                for (int j = 0; j < 4; j++) {
                    int s = __shfl_sync(FULLMASK, vidx, i + j);
                    int d = __shfl_sync(FULLMASK, vidx, 16 + i + j);
                    va[j] = *(const uint2*)(g_Y + (size_t)s * 256 + lane * 4);
                    vd[j] = *(const uint2*)(g_Y + (size_t)d * 256 + 128 + lane * 4);
                }
                #pragma unroll
                for (int j = 0; j < 4; j++) {
                    float2 fa0 = __half22float2(*(const __half2*)&va[j].x);
                    float2 fd0 = __half22float2(*(const __half2*)&vd[j].x);
                    float2 fa1 = __half22float2(*(const __half2*)&va[j].y);
                    float2 fd1 = __half22float2(*(const __half2*)&vd[j].y);
                    __half2 r0 = __floats2half2_rn(fmaxf(fa0.x + fd0.x + b1v.x, 0.f),
                                                   fmaxf(fa0.y + fd0.y + b1v.y, 0.f));
                    __half2 r1 = __floats2half2_rn(fmaxf(fa1.x + fd1.x + b1v.z, 0.f),
                                                   fmaxf(fa1.y + fd1.y + b1v.w, 0.f));
                    uint2 rv;
                    rv.x = *(const unsigned*)&r0;
                    rv.y = *(const unsigned*)&r1;
                    *(uint2*)(Hrow + (size_t)(i + j) * PADK) = rv;
                }
            }
        }
        __syncthreads();   // H ready; all warps past previous tile's MMA

        // ---- 32x64 warp-tile GEMM ----
        float acc[2][8][4];
        #pragma unroll
        for (int mi = 0; mi < 2; mi++)
            #pragma unroll
            for (int n8 = 0; n8 < 8; n8++)
                acc[mi][n8][0] = acc[mi][n8][1] = acc[mi][n8][2] = acc[mi][n8][3] = 0.f;

        warp_mma_32x64(Hs + (size_t)(wm * 32) * PADK,
                       Ws + (size_t)(wn * 64) * PADK, acc, lane);

        // ---- epilogue: shfl-merge lane pairs -> float4, +b2, STG.128 ----
        #pragma unroll
        for (int mi = 0; mi < 2; mi++) {
            const int r0 = e0 + wm * 32 + mi * 16 + g;
            #pragma unroll
            for (int q = 0; q < 4; q++) {
                const int n8e = 2 * q, n8o = 2 * q + 1;
                // send the group the partner needs; receive ours
                float s0 = oddt ? acc[mi][n8e][0] : acc[mi][n8o][0];
                float s1 = oddt ? acc[mi][n8e][1] : acc[mi][n8o][1];
                float s2 = oddt ? acc[mi][n8e][2] : acc[mi][n8o][2];
                float s3 = oddt ? acc[mi][n8e][3] : acc[mi][n8o][3];
                float x0 = __shfl_xor_sync(FULLMASK, s0, 1);
                float x1 = __shfl_xor_sync(FULLMASK, s1, 1);
                float x2 = __shfl_xor_sync(FULLMASK, s2, 1);
                float x3 = __shfl_xor_sync(FULLMASK, s3, 1);
                float4 v0, v1;
                if (!oddt) {
                    v0 = make_float4(acc[mi][n8e][0], acc[mi][n8e][1], x0, x1);
                    v1 = make_float4(acc[mi][n8e][2], acc[mi][n8e][3], x2, x3);
                } else {
                    v0 = make_float4(x0, x1, acc[mi][n8o][0], acc[mi][n8o][1]);
                    v1 = make_float4(x2, x3, acc[mi][n8o][2], acc[mi][n8o][3]);
                }
                v0.x += b2v[q].x; v0.y += b2v[q].y; v0.z += b2v[q].z; v0.w += b2v[q].w;
                v1.x += b2v[q].x; v1.y += b2v[q].y; v1.z += b2v[q].z; v1.w += b2v[q].w;
                if (r0 < n_edges)
                    *(float4*)(out + (size_t)r0 * 128 + colq[q]) = v0;
                if (r0 + 8 < n_edges)
                    *(float4*)(out + (size_t)(r0 + 8) * 128 + colq[q]) = v1;
            }
        }
        // no second sync: next iteration gathers into the other H buffer
    }
}

// ---------------------------------------------------------------------------
extern "C" void kernel_launch(void* const* d_in, const int* in_sizes, int n_in,
                              void* d_out, int out_size) {
    const float* x  = (const float*)d_in[0];
    const void*  ei = d_in[1];
    const float* W1 = (const float*)d_in[2];
    const float* b1 = (const float*)d_in[3];
    const float* W2 = (const float*)d_in[4];
    const float* b2 = (const float*)d_in[5];
    float* out = (float*)d_out;

    const int n_nodes = in_sizes[0] / 128;
    const int n_edges = in_sizes[1] / 2;

    const int smem3 = 3 * 128 * PADK * (int)sizeof(__half);   // 104448
    static bool attr_set = false;
    if (!attr_set) {
        cudaFuncSetAttribute(node_gemm_kernel,
                             cudaFuncAttributeMaxDynamicSharedMemorySize, smem3);
        cudaFuncSetAttribute(edge_kernel,
                             cudaFuncAttributeMaxDynamicSharedMemorySize, smem3);
        attr_set = true;
    }

    const int node_tiles = (n_nodes + 127) / 128;
    int g1x = node_tiles < 148 ? node_tiles : 148;
    dim3 g1(g1x, 2);
    node_gemm_kernel<<<g1, 256, smem3>>>(x, W1, ei, n_nodes);

    const int edge_tiles = (n_edges + 127) / 128;
    int g2 = edge_tiles < 296 ? edge_tiles : 296;
    edge_kernel<<<g2, 256, smem3>>>(ei, b1, W2, b2, out, n_edges);
}

// round 10
// speedup vs baseline: 1.2838x; 1.0131x over previous
#include <cuda_runtime.h>
#include <cuda_fp16.h>
#include <cstdint>

#define PADK 136           // halfs per smem row (128 + 8 pad) -> conflict-free LDSM
#define FULLMASK 0xffffffffu

// Scratch: per-node transformed features, fp16.
// Y[n, 0:128] = x[n] @ W1a (src half),  Y[n,128:256] = x[n] @ W1b (dst half)
__device__ __half g_Y[(size_t)50000 * 256];
__device__ int g_idx64;

// ---------------------------------------------------------------------------
__device__ __forceinline__ unsigned sptr(const void* p) {
    return (unsigned)__cvta_generic_to_shared(p);
}
__device__ __forceinline__ void ldsm4(unsigned a, unsigned& r0, unsigned& r1,
                                      unsigned& r2, unsigned& r3) {
    asm volatile("ldmatrix.sync.aligned.m8n8.x4.shared.b16 {%0,%1,%2,%3}, [%4];\n"
                 : "=r"(r0), "=r"(r1), "=r"(r2), "=r"(r3) : "r"(a));
}
__device__ __forceinline__ void mma16816(float* c, unsigned a0, unsigned a1,
                                         unsigned a2, unsigned a3,
                                         unsigned b0, unsigned b1) {
    asm volatile(
        "mma.sync.aligned.m16n8k16.row.col.f32.f16.f16.f32 "
        "{%0,%1,%2,%3}, {%4,%5,%6,%7}, {%8,%9}, {%0,%1,%2,%3};\n"
        : "+f"(c[0]), "+f"(c[1]), "+f"(c[2]), "+f"(c[3])
        : "r"(a0), "r"(a1), "r"(a2), "r"(a3), "r"(b0), "r"(b1));
}

// ---------------------------------------------------------------------------
// Warp-level 32x64x128 GEMM.
// ---------------------------------------------------------------------------
__device__ __forceinline__ void warp_mma_32x64(const __half* Aw, const __half* Bw,
                                               float acc[2][8][4], int lane) {
    unsigned a_addr = sptr(Aw + (size_t)(lane & 15) * PADK + ((lane & 16) ? 8 : 0));
    unsigned b_addr = sptr(Bw + (size_t)((lane & 7) + ((lane & 16) ? 8 : 0)) * PADK
                              + ((lane & 8) ? 8 : 0));
    #pragma unroll
    for (int k0 = 0; k0 < 128; k0 += 16) {
        unsigned a0[4], a1[4];
        ldsm4(a_addr + k0 * 2, a0[0], a0[1], a0[2], a0[3]);
        ldsm4(a_addr + 16 * PADK * 2 + k0 * 2, a1[0], a1[1], a1[2], a1[3]);
        #pragma unroll
        for (int np = 0; np < 4; np++) {
            unsigned b0, b1, b2, b3;
            ldsm4(b_addr + (unsigned)(np * 16 * PADK * 2) + k0 * 2, b0, b1, b2, b3);
            mma16816(acc[0][2 * np],     a0[0], a0[1], a0[2], a0[3], b0, b1);
            mma16816(acc[0][2 * np + 1], a0[0], a0[1], a0[2], a0[3], b2, b3);
            mma16816(acc[1][2 * np],     a1[0], a1[1], a1[2], a1[3], b0, b1);
            mma16816(acc[1][2 * np + 1], a1[0], a1[1], a1[2], a1[3], b2, b3);
        }
    }
}

// ---------------------------------------------------------------------------
// Node kernel (persistent, block 256, 2 CTAs/SM via y-split) — unchanged R9.
// ---------------------------------------------------------------------------
__global__ __launch_bounds__(256, 2)
void node_gemm_kernel(const float* __restrict__ x,
                      const float* __restrict__ W1,
                      const void* __restrict__ ei,
                      int n_nodes) {
    extern __shared__ __half smem[];
    __half* As0 = smem;                   // [128][PADK]
    __half* As1 = smem + 128 * PADK;
    __half* Ws  = smem + 2 * 128 * PADK;  // [128 cols][PADK k] for this half

    const int tid = threadIdx.x;
    const int half_sel = blockIdx.y;

    if (blockIdx.x == 0 && half_sel == 0 && tid < 32) {
        const unsigned* w = (const unsigned*)ei;
        unsigned v = w[2 * tid + 1] | w[2 * (tid + 32) + 1];
        int any_nz = __any_sync(FULLMASK, v != 0u);
        if (tid == 0) g_idx64 = any_nz ? 0 : 1;
    }

    for (int i = tid; i < 128 * 128; i += 256) {
        int k = i >> 7, n = i & 127;
        Ws[(size_t)n * PADK + k] =
            __float2half(W1[(size_t)(k + (half_sel << 7)) * 128 + n]);
    }

    const int warp = tid >> 5, lane = tid & 31;
    const int wm = warp & 3, wn = warp >> 2;   // 4M x 2N
    const int g = lane >> 2, t = lane & 3;
    const int n_tiles = (n_nodes + 127) >> 7;

    int li = 0;
    for (int tile = blockIdx.x; tile < n_tiles; tile += gridDim.x, li++) {
        __half* As = (li & 1) ? As1 : As0;
        const int row0 = tile << 7;

        for (int i = tid; i < 128 * 32; i += 256) {
            int r = i >> 5, c4 = i & 31;
            int gr = row0 + r;
            float4 v = make_float4(0.f, 0.f, 0.f, 0.f);
            if (gr < n_nodes) v = ((const float4*)x)[(size_t)gr * 32 + c4];
            __half* dst = As + (size_t)r * PADK + c4 * 4;
            dst[0] = __float2half(v.x); dst[1] = __float2half(v.y);
            dst[2] = __float2half(v.z); dst[3] = __float2half(v.w);
        }
        __syncthreads();

        float acc[2][8][4];
        #pragma unroll
        for (int mi = 0; mi < 2; mi++)
            #pragma unroll
            for (int n8 = 0; n8 < 8; n8++)
                acc[mi][n8][0] = acc[mi][n8][1] = acc[mi][n8][2] = acc[mi][n8][3] = 0.f;

        warp_mma_32x64(As + (size_t)(wm * 32) * PADK,
                       Ws + (size_t)(wn * 64) * PADK, acc, lane);

        __half* Yb = g_Y + (half_sel << 7);
        #pragma unroll
        for (int mi = 0; mi < 2; mi++) {
            const int r0 = row0 + wm * 32 + mi * 16 + g;
            #pragma unroll
            for (int n8 = 0; n8 < 8; n8++) {
                int col = wn * 64 + n8 * 8 + 2 * t;
                if (r0 < n_nodes)
                    *(__half2*)(Yb + (size_t)r0 * 256 + col) =
                        __floats2half2_rn(acc[mi][n8][0], acc[mi][n8][1]);
                if (r0 + 8 < n_nodes)
                    *(__half2*)(Yb + (size_t)(r0 + 8) * 256 + col) =
                        __floats2half2_rn(acc[mi][n8][2], acc[mi][n8][3]);
            }
        }
    }
}

// ---------------------------------------------------------------------------
// Edge kernel (persistent, block 256, 2 CTAs/SM) — R9 base, latency cuts:
//  * next-tile index LDG issued before MMA (latency hidden under MMA)
//  * gather batched x8 (2 exposed L2 waves instead of 4)
//  * half2 gather arithmetic (3 ops/half2 instead of 9)
// ---------------------------------------------------------------------------
__global__ __launch_bounds__(256, 2)
void edge_kernel(const void* __restrict__ edge_index,
                 const float* __restrict__ b1,
                 const float* __restrict__ W2,
                 const float* __restrict__ b2,
                 float* __restrict__ out,
                 int n_edges) {
    extern __shared__ __half smem[];
    __half* Hs0 = smem;                   // [128][PADK]
    __half* Hs1 = smem + 128 * PADK;
    __half* Ws  = smem + 2 * 128 * PADK;  // [128 n][PADK k] = W2[k][n]

    const int tid = threadIdx.x;
    const int warp = tid >> 5, lane = tid & 31;
    const int wm = warp & 3, wn = warp >> 2;   // 4M x 2N
    const int g = lane >> 2, t = lane & 3;
    const bool oddt = (t & 1);

    // Stage W2 once (transposed; coalesced on global side)
    for (int i = tid; i < 128 * 128; i += 256) {
        int k = i >> 7, n = i & 127;
        Ws[(size_t)n * PADK + k] = __float2half(W2[i]);  // W2[k*128+n]
    }

    // Per-lane constants
    const float4 b1v = *(const float4*)(b1 + lane * 4);
    const __half2 b1h0 = __floats2half2_rn(b1v.x, b1v.y);
    const __half2 b1h1 = __floats2half2_rn(b1v.z, b1v.w);
    const __half2 hzero = __float2half2_rn(0.f);

    int colq[4];
    float4 b2v[4];
    #pragma unroll
    for (int q = 0; q < 4; q++) {
        colq[q] = wn * 64 + 16 * q + (oddt ? 8 + 2 * (t - 1) : 2 * t);
        b2v[q] = *(const float4*)(b2 + colq[q]);
    }

    const int is64 = g_idx64;
    const long long* idx64 = (const long long*)edge_index;
    const int*       idx32 = (const int*)edge_index;
    const int n_tiles = (n_edges + 127) >> 7;

    auto load_idx = [&](int tl) -> int {
        int myE = (tl << 7) + (warp << 4) + (lane & 15);
        if (myE >= n_edges) myE = n_edges - 1;
        size_t off = (lane < 16) ? (size_t)myE : (size_t)n_edges + (size_t)myE;
        return is64 ? (int)idx64[off] : idx32[off];
    };

    int tile = blockIdx.x;
    if (tile >= n_tiles) return;
    int vidx = load_idx(tile);   // prologue index load (covered by Ws staging)

    int li = 0;
    while (true) {
        __half* Hs = (li & 1) ? Hs1 : Hs0;
        const int e0 = tile << 7;

        // ---- warp-cooperative gather, batch x8, half2 math ----
        {
            __half* Hrow = Hs + (size_t)(warp << 4) * PADK + lane * 4;
            #pragma unroll
            for (int i = 0; i < 16; i += 8) {
                uint2 va[8], vd[8];
                #pragma unroll
                for (int j = 0; j < 8; j++) {
                    int s = __shfl_sync(FULLMASK, vidx, i + j);
                    int d = __shfl_sync(FULLMASK, vidx, 16 + i + j);
                    va[j] = *(const uint2*)(g_Y + (size_t)s * 256 + lane * 4);
                    vd[j] = *(const uint2*)(g_Y + (size_t)d * 256 + 128 + lane * 4);
                }
                #pragma unroll
                for (int j = 0; j < 8; j++) {
                    __half2 s0 = *(const __half2*)&va[j].x;
                    __half2 s1 = *(const __half2*)&va[j].y;
                    __half2 d0 = *(const __half2*)&vd[j].x;
                    __half2 d1 = *(const __half2*)&vd[j].y;
                    __half2 r0 = __hmax2(__hadd2(__hadd2(s0, d0), b1h0), hzero);
                    __half2 r1 = __hmax2(__hadd2(__hadd2(s1, d1), b1h1), hzero);
                    uint2 rv;
                    rv.x = *(const unsigned*)&r0;
                    rv.y = *(const unsigned*)&r1;
                    *(uint2*)(Hrow + (size_t)(i + j) * PADK) = rv;
                }
            }
        }
        __syncthreads();   // H ready; all warps past previous tile's MMA

        // ---- prefetch next tile's indices (latency hidden under MMA) ----
        const int next = tile + gridDim.x;
        const bool more = next < n_tiles;
        int vnext = more ? load_idx(next) : 0;

        // ---- 32x64 warp-tile GEMM ----
        float acc[2][8][4];
        #pragma unroll
        for (int mi = 0; mi < 2; mi++)
            #pragma unroll
            for (int n8 = 0; n8 < 8; n8++)
                acc[mi][n8][0] = acc[mi][n8][1] = acc[mi][n8][2] = acc[mi][n8][3] = 0.f;

        warp_mma_32x64(Hs + (size_t)(wm * 32) * PADK,
                       Ws + (size_t)(wn * 64) * PADK, acc, lane);

        // ---- epilogue: shfl-merge lane pairs -> float4, +b2, STG.128 ----
        #pragma unroll
        for (int mi = 0; mi < 2; mi++) {
            const int r0 = e0 + wm * 32 + mi * 16 + g;
            #pragma unroll
            for (int q = 0; q < 4; q++) {
                const int n8e = 2 * q, n8o = 2 * q + 1;
                float s0 = oddt ? acc[mi][n8e][0] : acc[mi][n8o][0];
                float s1 = oddt ? acc[mi][n8e][1] : acc[mi][n8o][1];
                float s2 = oddt ? acc[mi][n8e][2] : acc[mi][n8o][2];
                float s3 = oddt ? acc[mi][n8e][3] : acc[mi][n8o][3];
                float x0 = __shfl_xor_sync(FULLMASK, s0, 1);
                float x1 = __shfl_xor_sync(FULLMASK, s1, 1);
                float x2 = __shfl_xor_sync(FULLMASK, s2, 1);
                float x3 = __shfl_xor_sync(FULLMASK, s3, 1);
                float4 v0, v1;
                if (!oddt) {
                    v0 = make_float4(acc[mi][n8e][0], acc[mi][n8e][1], x0, x1);
                    v1 = make_float4(acc[mi][n8e][2], acc[mi][n8e][3], x2, x3);
                } else {
                    v0 = make_float4(x0, x1, acc[mi][n8o][0], acc[mi][n8o][1]);
                    v1 = make_float4(x2, x3, acc[mi][n8o][2], acc[mi][n8o][3]);
                }
                v0.x += b2v[q].x; v0.y += b2v[q].y; v0.z += b2v[q].z; v0.w += b2v[q].w;
                v1.x += b2v[q].x; v1.y += b2v[q].y; v1.z += b2v[q].z; v1.w += b2v[q].w;
                if (r0 < n_edges)
                    *(float4*)(out + (size_t)r0 * 128 + colq[q]) = v0;
                if (r0 + 8 < n_edges)
                    *(float4*)(out + (size_t)(r0 + 8) * 128 + colq[q]) = v1;
            }
        }

        if (!more) break;
        tile = next; vidx = vnext; li++;
        // no extra sync: ping-pong H; next gather targets the other buffer
    }
}

// ---------------------------------------------------------------------------
extern "C" void kernel_launch(void* const* d_in, const int* in_sizes, int n_in,
                              void* d_out, int out_size) {
    const float* x  = (const float*)d_in[0];
    const void*  ei = d_in[1];
    const float* W1 = (const float*)d_in[2];
    const float* b1 = (const float*)d_in[3];
    const float* W2 = (const float*)d_in[4];
    const float* b2 = (const float*)d_in[5];
    float* out = (float*)d_out;

    const int n_nodes = in_sizes[0] / 128;
    const int n_edges = in_sizes[1] / 2;

    const int smem3 = 3 * 128 * PADK * (int)sizeof(__half);   // 104448
    static bool attr_set = false;
    if (!attr_set) {
        cudaFuncSetAttribute(node_gemm_kernel,
                             cudaFuncAttributeMaxDynamicSharedMemorySize, smem3);
        cudaFuncSetAttribute(edge_kernel,
                             cudaFuncAttributeMaxDynamicSharedMemorySize, smem3);
        attr_set = true;
    }

    const int node_tiles = (n_nodes + 127) / 128;
    int g1x = node_tiles < 148 ? node_tiles : 148;
    dim3 g1(g1x, 2);
    node_gemm_kernel<<<g1, 256, smem3>>>(x, W1, ei, n_nodes);

    const int edge_tiles = (n_edges + 127) / 128;
    int g2 = edge_tiles < 296 ? edge_tiles : 296;
    edge_kernel<<<g2, 256, smem3>>>(ei, b1, W2, b2, out, n_edges);
}